// round 11
// baseline (speedup 1.0000x reference)
#include <cuda_runtime.h>
#include <cstdint>

#define EMB_DIM  128
#define NB_WORDS 100000
#define RPT      4

// out[b][e] = W[e * NB_WORDS + elt[b]] + bias[e]
// 512 threads = 4 lane-groups of 128; each thread handles RPT=4 batch rows,
// all 4 scattered gathers front-batched (whole problem in flight in 1 wave).
__global__ void __launch_bounds__(512)
time_embedding_kernel(const int* __restrict__ elt,
                      const float* __restrict__ W,
                      const float* __restrict__ bias,
                      float* __restrict__ out,
                      int batch) {
    const int e    = threadIdx.x & (EMB_DIM - 1);   // 0..127
    const int sub  = threadIdx.x >> 7;              // 0..3
    const int row0 = blockIdx.x * (4 * RPT) + sub * RPT;

    // L2 policies: W -> evict_last (retain across graph replays),
    // out -> evict_first (streaming, don't displace W).
    uint64_t pol_last, pol_first;
    asm volatile("createpolicy.fractional.L2::evict_last.b64 %0, 1.0;"
                 : "=l"(pol_last));
    asm volatile("createpolicy.fractional.L2::evict_first.b64 %0, 1.0;"
                 : "=l"(pol_first));

    const float bv = __ldg(&bias[e]);
    const float* Wrow = W + (size_t)e * NB_WORDS;

    // Front-batch index loads (warp-uniform broadcasts).
    int idx[RPT];
    #pragma unroll
    for (int k = 0; k < RPT; k++) {
        const int b = row0 + k;
        idx[k] = (b < batch) ? __ldg(&elt[b]) : 0;
    }

    // Front-batch 4 independent gathers: 64B fills, L2-pinned.
    float w[RPT];
    #pragma unroll
    for (int k = 0; k < RPT; k++) {
        asm volatile("ld.global.nc.L2::cache_hint.L2::64B.f32 %0, [%1], %2;"
                     : "=f"(w[k]) : "l"(Wrow + idx[k]), "l"(pol_last));
    }

    #pragma unroll
    for (int k = 0; k < RPT; k++) {
        const int b = row0 + k;
        if (b < batch) {
            const float val = w[k] + bv;
            asm volatile("st.global.L2::cache_hint.f32 [%0], %1, %2;"
                         :: "l"(&out[(size_t)b * EMB_DIM + e]), "f"(val),
                            "l"(pol_first) : "memory");
        }
    }
}

extern "C" void kernel_launch(void* const* d_in, const int* in_sizes, int n_in,
                              void* d_out, int out_size) {
    const int* elt  = (const int*)d_in[0];
    const float* W  = (const float*)d_in[1];
    const float* bv = (const float*)d_in[2];
    float* out      = (float*)d_out;
    const int batch = in_sizes[0];                  // 4096

    const int rows_per_block = 4 * RPT;             // 16
    const int blocks = (batch + rows_per_block - 1) / rows_per_block;  // 256
    time_embedding_kernel<<<blocks, 512>>>(elt, W, bv, out, batch);
}